// round 1
// baseline (speedup 1.0000x reference)
#include <cuda_runtime.h>
#include <math.h>

// Problem constants
#define SS 3       // REFINE_LAYERS
#define BB 32      // batch
#define NN 2000    // priors
#define LL 4       // max lanes
#define DD 78      // 2 + 4 + 72
#define NP 72      // num points offsets

// Scratch (device globals; no allocation allowed)
__device__ float  g_cost[2][SS][BB][NN][LL];
__device__ float2 g_clslog[2][SS][BB][NN];
__device__ int    g_rows[2][SS][BB][LL];
__device__ float  g_inst[2][NN];
__device__ float  g_regpart[2][SS][BB][LL];
__device__ float  g_ioupart[2][SS][BB][LL];

// ---------------------------------------------------------------------------
// Kernel 1: cost matrix + per-prior log-softmax.
// One warp per (branch, s, b, n). 8 warps/block; N % 8 == 0 so every block has
// a single (branch,s,b) -> stage gt rows for that b in shared.
// ---------------------------------------------------------------------------
__global__ void k_cost(const float* __restrict__ pA,
                       const float* __restrict__ pB,
                       const float* __restrict__ gt) {
    __shared__ float sgt[LL * DD];  // 312 floats
    const int wib  = threadIdx.x >> 5;
    const int lane = threadIdx.x & 31;
    long gw = (long)blockIdx.x * 8 + wib;   // global warp id

    int n = (int)(gw % NN); long t = gw / NN;
    int b = (int)(t % BB);  t /= BB;
    int s = (int)(t % SS);  t /= SS;
    int br = (int)t;        // branch 0/1

    // stage gt[b] (4 rows x 78 floats, contiguous)
    for (int i = threadIdx.x; i < LL * DD; i += blockDim.x)
        sgt[i] = gt[b * LL * DD + i];
    __syncthreads();

    const float* p = (br == 0 ? pA : pB) + ((size_t)((s * BB + b) * NN + n)) * DD;

    float v0 = p[lane];
    float v1 = p[lane + 32];
    float v2 = (lane < DD - 64) ? p[lane + 64] : 0.0f;

    float p0 = __shfl_sync(0xffffffffu, v0, 0);
    float p1 = __shfl_sync(0xffffffffu, v0, 1);
    float mx = fmaxf(p0, p1);
    float lse = mx + logf(expf(p0 - mx) + expf(p1 - mx));
    float lp0 = p0 - lse, lp1 = p1 - lse;
    float score = expf(lp1);

    float c[LL];
    #pragma unroll
    for (int l = 0; l < LL; l++) {
        const float* tg = &sgt[l * DD];
        float t0 = tg[lane];
        float t1 = tg[lane + 32];
        float t2 = (lane < DD - 64) ? tg[lane + 64] : 0.0f;

        float geo = (lane >= 2 && lane < 6) ? fabsf(v0 - t0) : 0.0f;
        float off = 0.0f;
        if (lane >= 6)          off += fabsf(v0 - t0 / 799.0f);
                                off += fabsf(v1 - t1 / 799.0f);
        if (lane < DD - 64)     off += fabsf(v2 - t2 / 799.0f);
        c[l] = geo + off * (1.0f / 72.0f);
    }
    #pragma unroll
    for (int l = 0; l < LL; l++) {
        #pragma unroll
        for (int o = 16; o; o >>= 1)
            c[l] += __shfl_xor_sync(0xffffffffu, c[l], o);
    }
    if (lane == 0) {
        #pragma unroll
        for (int l = 0; l < LL; l++)
            g_cost[br][s][b][n][l] = c[l] - score;
        g_clslog[br][s][b][n] = make_float2(lp0, lp1);
    }
}

// ---------------------------------------------------------------------------
// Kernel 2: greedy assignment without replacement, per (branch,s,b).
// L=4 sequential argmins over N; tie-break = lowest index (jnp.argmin).
// ---------------------------------------------------------------------------
__global__ void k_assign() {
    int b = blockIdx.x % BB; int t = blockIdx.x / BB;
    int s = t % SS; int br = t / SS;
    const float* cost = &g_cost[br][s][b][0][0];

    __shared__ float sv[256];
    __shared__ int   si[256];
    __shared__ int   chosen[LL];

    for (int l = 0; l < LL; l++) {
        float best = INFINITY; int bi = NN;
        for (int n = threadIdx.x; n < NN; n += blockDim.x) {
            bool used = false;
            for (int j = 0; j < l; j++) used |= (chosen[j] == n);
            float v = used ? INFINITY : cost[n * LL + l];
            if (v < best) { best = v; bi = n; }
        }
        sv[threadIdx.x] = best; si[threadIdx.x] = bi;
        __syncthreads();
        for (int o = 128; o; o >>= 1) {
            if ((int)threadIdx.x < o) {
                float ov = sv[threadIdx.x + o]; int oi = si[threadIdx.x + o];
                if (ov < sv[threadIdx.x] ||
                    (ov == sv[threadIdx.x] && oi < si[threadIdx.x])) {
                    sv[threadIdx.x] = ov; si[threadIdx.x] = oi;
                }
            }
            __syncthreads();
        }
        if (threadIdx.x == 0) { chosen[l] = si[0]; g_rows[br][s][b][l] = si[0]; }
        __syncthreads();
    }
}

// ---------------------------------------------------------------------------
// Kernel 3: focal classification loss per prior -> g_inst (already * CLS_W).
// ---------------------------------------------------------------------------
__global__ void k_cls() {
    int idx = blockIdx.x * blockDim.x + threadIdx.x;
    if (idx >= 2 * NN) return;
    int br = idx / NN, n = idx % NN;
    float acc = 0.0f;
    for (int s = 0; s < SS; s++) {
        for (int b = 0; b < BB; b++) {
            float2 lp = g_clslog[br][s][b][n];
            const int* r = g_rows[br][s][b];
            bool matched = (r[0] == n) | (r[1] == n) | (r[2] == n) | (r[3] == n);
            float logpt = matched ? lp.y : lp.x;
            float pt = expf(logpt);
            float a = matched ? 0.9f : 0.1f;
            float om = 1.0f - pt;
            acc += -a * om * om * logpt;
        }
    }
    g_inst[br][n] = acc * (1.0f / 96.0f) * 2.0f;  // /(B*S), * CLS_W
}

// ---------------------------------------------------------------------------
// Kernel 4: matched-prior smooth-L1 + line-IoU partials. One warp per
// (branch,s,b,l).
// ---------------------------------------------------------------------------
__global__ void k_matched(const float* __restrict__ pA,
                          const float* __restrict__ pB,
                          const float* __restrict__ gt) {
    int id = blockIdx.x;                 // [0, 2*S*B*L)
    int l = id % LL; int t = id / LL;
    int b = t % BB;  t /= BB;
    int s = t % SS;  int br = t / SS;
    int lane = threadIdx.x;

    int r = g_rows[br][s][b][l];
    const float* pm = (br ? pB : pA) + ((size_t)((s * BB + b) * NN + r)) * DD;
    const float* tg = gt + (b * LL + l) * DD;

    // smooth-L1 on dims 2..5
    float sl = 0.0f;
    if (lane < 4) {
        const float scv[4] = {71.0f, 799.0f, 180.0f, 71.0f};
        float d = pm[2 + lane] * scv[lane] - tg[2 + lane] * scv[lane];
        float ad = fabsf(d);
        sl = (ad < 1.0f) ? 0.5f * d * d : ad - 0.5f;
    }
    // line IoU over 72 offsets
    float ovr = 0.0f, uni = 0.0f;
    for (int j = lane; j < NP; j += 32) {
        float rp = pm[6 + j] * 799.0f;
        float rt = tg[6 + j];
        bool inv = (rt < 0.0f) || (rt >= 800.0f);
        float o = fminf(rp + 15.0f, rt + 15.0f) - fmaxf(rp - 15.0f, rt - 15.0f);
        float u = fmaxf(rp + 15.0f, rt + 15.0f) - fminf(rp - 15.0f, rt - 15.0f);
        if (!inv) { ovr += o; uni += u; }
    }
    #pragma unroll
    for (int o = 16; o; o >>= 1) {
        sl  += __shfl_xor_sync(0xffffffffu, sl,  o);
        ovr += __shfl_xor_sync(0xffffffffu, ovr, o);
        uni += __shfl_xor_sync(0xffffffffu, uni, o);
    }
    if (lane == 0) {
        float iou = ovr / (uni + 1e-9f);
        g_regpart[br][s][b][l] = (sl * 0.25f) / (float)LL;  // mean(4)/L
        g_ioupart[br][s][b][l] = (1.0f - iou) / (float)LL;
    }
}

// ---------------------------------------------------------------------------
// Kernel 5: finalize. reg/iou reduce + scatter into inst, median(diff of
// inst arrays), weighted sum.
// ---------------------------------------------------------------------------
__global__ void k_final(const float* __restrict__ diff, float* __restrict__ out) {
    __shared__ float sx[NN];
    __shared__ float sred[1024];
    __shared__ float s_m0, s_m1;
    int tid = threadIdx.x;

    // step 1: per-(branch,l) deterministic reduce + inst scatter
    if (tid < 2 * LL) {
        int br = tid / LL, l = tid % LL;
        float rs = 0.0f, is = 0.0f;
        for (int s = 0; s < SS; s++)
            for (int b = 0; b < BB; b++) {
                rs += g_regpart[br][s][b][l];
                is += g_ioupart[br][s][b][l];
            }
        rs *= (1.0f / 96.0f);
        is *= (1.0f / 96.0f);
        int row = g_rows[br][SS - 1][BB - 1][l];
        g_inst[br][row] += rs * 0.5f + is * 2.0f;  // REG_W, IOU_W
    }
    __syncthreads();

    // step 2: x = instA - instB
    for (int n = tid; n < NN; n += blockDim.x)
        sx[n] = g_inst[0][n] - g_inst[1][n];
    __syncthreads();

    // step 3: median via counting selection (order stats 999 & 1000)
    for (int i = tid; i < NN; i += blockDim.x) {
        float v = sx[i];
        int cl = 0, ce = 0;
        for (int j = 0; j < NN; j++) {
            float w = sx[j];
            cl += (w < v);
            ce += (w == v);
        }
        if (cl <= 999 && 999 < cl + ce)  s_m0 = v;
        if (cl <= 1000 && 1000 < cl + ce) s_m1 = v;
    }
    __syncthreads();
    float delta = 0.5f * (s_m0 + s_m1);

    // step 4: total = sum (1-dm)*(A - d/2) + dm*(B + d/2)
    float acc = 0.0f;
    for (int n = tid; n < NN; n += blockDim.x) {
        float dm = (diff[n] + diff[NN + n] + diff[2 * NN + n]) * (1.0f / 3.0f);
        acc += (1.0f - dm) * (g_inst[0][n] - 0.5f * delta)
             + dm * (g_inst[1][n] + 0.5f * delta);
    }
    sred[tid] = acc;
    __syncthreads();
    for (int o = 512; o; o >>= 1) {
        if (tid < o) sred[tid] += sred[tid + o];
        __syncthreads();
    }
    if (tid == 0) out[0] = sred[0];
}

// ---------------------------------------------------------------------------
extern "C" void kernel_launch(void* const* d_in, const int* in_sizes, int n_in,
                              void* d_out, int out_size) {
    const float* pA   = (const float*)d_in[0];  // predictions_fir [S,B,N,D]
    const float* pB   = (const float*)d_in[1];  // predictions_sec [S,B,N,D]
    const float* gt   = (const float*)d_in[2];  // gt_lane [B,L,D]
    const float* diff = (const float*)d_in[3];  // diff [S,N]
    float* out = (float*)d_out;

    // total warps = 2*S*B*N = 384000; 8 warps/block
    int blocks_cost = (2 * SS * BB * NN) / 8;   // 48000
    k_cost<<<blocks_cost, 256>>>(pA, pB, gt);

    k_assign<<<2 * SS * BB, 256>>>();           // 192 blocks

    k_cls<<<(2 * NN + 255) / 256, 256>>>();     // 16 blocks

    k_matched<<<2 * SS * BB * LL, 32>>>(pA, pB, gt);  // 768 warps

    k_final<<<1, 1024>>>(diff, out);
}

// round 2
// speedup vs baseline: 2.3107x; 2.3107x over previous
#include <cuda_runtime.h>
#include <math.h>

// Problem constants
#define SS 3       // REFINE_LAYERS
#define BB 32      // batch
#define NN 2000    // priors
#define LL 4       // max lanes
#define DD 78      // 2 + 4 + 72
#define NP 72      // num points offsets

// Scratch (device globals; no allocation allowed)
__device__ float  g_cost[2][SS][BB][LL][NN];   // transposed: coalesced argmin reads
__device__ float2 g_clslog[2][SS][BB][NN];
__device__ int    g_rows[2][SS][BB][LL];
__device__ float  g_inst[2][NN];
__device__ float  g_regpart[2][SS][BB][LL];
__device__ float  g_ioupart[2][SS][BB][LL];

// ---------------------------------------------------------------------------
// Kernel 1: cost matrix + per-prior log-softmax.
// One warp per (branch, s, b, n). 8 warps/block; NN % 8 == 0 so every block
// has a single (branch,s,b) -> stage gt rows for that b in shared, with the
// /799 division done ONCE during staging (same fp32 division as reference).
// ---------------------------------------------------------------------------
__global__ void k_cost(const float* __restrict__ pA,
                       const float* __restrict__ pB,
                       const float* __restrict__ gt) {
    __shared__ float sq[LL][NP];    // gt offsets / 799
    __shared__ float sraw[LL][4];   // raw gt dims 2..5 (geo)
    const int wib  = threadIdx.x >> 5;
    const int lane = threadIdx.x & 31;
    int gw = blockIdx.x * 8 + wib;

    int n = gw % NN; int t = gw / NN;
    int b = t % BB;  t /= BB;
    int s = t % SS;  int br = t / SS;

    for (int i = threadIdx.x; i < LL * DD; i += 256) {
        int l = i / DD, d = i % DD;
        float v = gt[b * LL * DD + i];
        if (d >= 6)      sq[l][d - 6]   = v / 799.0f;
        else if (d >= 2) sraw[l][d - 2] = v;
    }
    __syncthreads();

    const float* p = (br ? pB : pA) + ((size_t)((s * BB + b) * NN + n)) * DD;
    float v0 = p[lane];
    float v1 = p[lane + 32];
    float v2 = (lane < 14) ? p[lane + 64] : 0.0f;

    float p0 = __shfl_sync(0xffffffffu, v0, 0);
    float p1 = __shfl_sync(0xffffffffu, v0, 1);
    float mx = fmaxf(p0, p1);
    float lse = mx + logf(expf(p0 - mx) + expf(p1 - mx));
    float lp0 = p0 - lse, lp1 = p1 - lse;
    float score = expf(lp1);

    float c[LL];
    #pragma unroll
    for (int l = 0; l < LL; l++) {
        float off = 0.0f, geo = 0.0f;
        if (lane >= 6)      off  = fabsf(v0 - sq[l][lane - 6]);
        else if (lane >= 2) geo  = fabsf(v0 - sraw[l][lane - 2]);
        off += fabsf(v1 - sq[l][lane + 26]);
        if (lane < 14) off += fabsf(v2 - sq[l][lane + 58]);
        c[l] = geo + off * (1.0f / 72.0f);
    }
    #pragma unroll
    for (int l = 0; l < LL; l++) {
        #pragma unroll
        for (int o = 16; o; o >>= 1)
            c[l] += __shfl_xor_sync(0xffffffffu, c[l], o);
    }
    if (lane == 0) {
        #pragma unroll
        for (int l = 0; l < LL; l++)
            g_cost[br][s][b][l][n] = c[l] - score;
        g_clslog[br][s][b][n] = make_float2(lp0, lp1);
    }
}

// ---------------------------------------------------------------------------
// Kernel 2: greedy assignment without replacement, per (branch,s,b).
// L=4 sequential argmins over N; tie-break = lowest index (jnp.argmin).
// Reads are now stride-1 coalesced.
// ---------------------------------------------------------------------------
__global__ void k_assign() {
    int b = blockIdx.x % BB; int t = blockIdx.x / BB;
    int s = t % SS; int br = t / SS;

    __shared__ float sv[256];
    __shared__ int   si[256];
    __shared__ int   chosen[LL];

    for (int l = 0; l < LL; l++) {
        const float* cost = &g_cost[br][s][b][l][0];
        float best = INFINITY; int bi = NN;
        for (int n = threadIdx.x; n < NN; n += 256) {
            bool used = false;
            for (int j = 0; j < l; j++) used |= (chosen[j] == n);
            float v = used ? INFINITY : cost[n];
            if (v < best) { best = v; bi = n; }
        }
        sv[threadIdx.x] = best; si[threadIdx.x] = bi;
        __syncthreads();
        for (int o = 128; o; o >>= 1) {
            if ((int)threadIdx.x < o) {
                float ov = sv[threadIdx.x + o]; int oi = si[threadIdx.x + o];
                if (ov < sv[threadIdx.x] ||
                    (ov == sv[threadIdx.x] && oi < si[threadIdx.x])) {
                    sv[threadIdx.x] = ov; si[threadIdx.x] = oi;
                }
            }
            __syncthreads();
        }
        if (threadIdx.x == 0) { chosen[l] = si[0]; g_rows[br][s][b][l] = si[0]; }
        __syncthreads();
    }
}

// ---------------------------------------------------------------------------
// Kernel 3: focal classification loss per prior -> g_inst (already * CLS_W).
// grid = (8, 2): blockIdx.y = branch; rows staged in shared; __expf.
// ---------------------------------------------------------------------------
__global__ void k_cls() {
    __shared__ int srows[SS * BB * LL];   // 384
    int br = blockIdx.y;
    int n  = blockIdx.x * 256 + threadIdx.x;

    const int* rsrc = &g_rows[br][0][0][0];
    for (int i = threadIdx.x; i < SS * BB * LL; i += 256) srows[i] = rsrc[i];
    __syncthreads();
    if (n >= NN) return;

    const float2* lpbase = &g_clslog[br][0][0][0];
    float acc = 0.0f;
    #pragma unroll 4
    for (int sb = 0; sb < SS * BB; sb++) {
        float2 lp = lpbase[sb * NN + n];
        const int* r = &srows[sb * 4];
        bool matched = (r[0] == n) | (r[1] == n) | (r[2] == n) | (r[3] == n);
        float logpt = matched ? lp.y : lp.x;
        float pt = __expf(logpt);
        float a = matched ? 0.9f : 0.1f;
        float om = 1.0f - pt;
        acc += -a * om * om * logpt;
    }
    g_inst[br][n] = acc * (1.0f / 96.0f) * 2.0f;  // /(B*S), * CLS_W
}

// ---------------------------------------------------------------------------
// Kernel 4: matched-prior smooth-L1 + line-IoU partials. One warp per
// (branch,s,b,l).
// ---------------------------------------------------------------------------
__global__ void k_matched(const float* __restrict__ pA,
                          const float* __restrict__ pB,
                          const float* __restrict__ gt) {
    int id = blockIdx.x;                 // [0, 2*S*B*L)
    int l = id % LL; int t = id / LL;
    int b = t % BB;  t /= BB;
    int s = t % SS;  int br = t / SS;
    int lane = threadIdx.x;

    int r = g_rows[br][s][b][l];
    const float* pm = (br ? pB : pA) + ((size_t)((s * BB + b) * NN + r)) * DD;
    const float* tg = gt + (b * LL + l) * DD;

    float sl = 0.0f;
    if (lane < 4) {
        const float scv[4] = {71.0f, 799.0f, 180.0f, 71.0f};
        float d = pm[2 + lane] * scv[lane] - tg[2 + lane] * scv[lane];
        float ad = fabsf(d);
        sl = (ad < 1.0f) ? 0.5f * d * d : ad - 0.5f;
    }
    float ovr = 0.0f, uni = 0.0f;
    for (int j = lane; j < NP; j += 32) {
        float rp = pm[6 + j] * 799.0f;
        float rt = tg[6 + j];
        bool inv = (rt < 0.0f) || (rt >= 800.0f);
        float o = fminf(rp + 15.0f, rt + 15.0f) - fmaxf(rp - 15.0f, rt - 15.0f);
        float u = fmaxf(rp + 15.0f, rt + 15.0f) - fminf(rp - 15.0f, rt - 15.0f);
        if (!inv) { ovr += o; uni += u; }
    }
    #pragma unroll
    for (int o = 16; o; o >>= 1) {
        sl  += __shfl_xor_sync(0xffffffffu, sl,  o);
        ovr += __shfl_xor_sync(0xffffffffu, ovr, o);
        uni += __shfl_xor_sync(0xffffffffu, uni, o);
    }
    if (lane == 0) {
        float iou = ovr / (uni + 1e-9f);
        g_regpart[br][s][b][l] = (sl * 0.25f) / (float)LL;
        g_ioupart[br][s][b][l] = (1.0f - iou) / (float)LL;
    }
}

// ---------------------------------------------------------------------------
// Kernel 5: finalize. reg/iou reduce + scatter into inst, median via bitonic
// sort (2048 padded), weighted sum.
// ---------------------------------------------------------------------------
__global__ void k_final(const float* __restrict__ diff, float* __restrict__ out) {
    __shared__ float sx[2048];
    __shared__ float sred[1024];
    int tid = threadIdx.x;

    // step 1: per-(branch,l) deterministic reduce + inst scatter
    if (tid < 2 * LL) {
        int br = tid >> 2, l = tid & 3;
        const float* rp = &g_regpart[br][0][0][0];
        const float* ip = &g_ioupart[br][0][0][0];
        float rs = 0.0f, is = 0.0f;
        for (int sb = 0; sb < SS * BB; sb++) {
            rs += rp[sb * LL + l];
            is += ip[sb * LL + l];
        }
        rs *= (1.0f / 96.0f);
        is *= (1.0f / 96.0f);
        int row = g_rows[br][SS - 1][BB - 1][l];
        g_inst[br][row] += rs * 0.5f + is * 2.0f;  // REG_W, IOU_W
    }
    __syncthreads();

    // step 2: x = instA - instB, padded to 2048 with +inf
    for (int n = tid; n < 2048; n += 1024)
        sx[n] = (n < NN) ? (g_inst[0][n] - g_inst[1][n]) : INFINITY;

    // step 3: bitonic sort ascending
    for (int k = 2; k <= 2048; k <<= 1) {
        for (int j = k >> 1; j > 0; j >>= 1) {
            __syncthreads();
            for (int i = tid; i < 2048; i += 1024) {
                int ixj = i ^ j;
                if (ixj > i) {
                    float a = sx[i], bb2 = sx[ixj];
                    bool up = ((i & k) == 0);
                    if ((a > bb2) == up) { sx[i] = bb2; sx[ixj] = a; }
                }
            }
        }
    }
    __syncthreads();
    float delta = 0.5f * (sx[999] + sx[1000]);

    // step 4: total = sum (1-dm)*(A - d/2) + dm*(B + d/2)
    float acc = 0.0f;
    for (int n = tid; n < NN; n += 1024) {
        float dm = (diff[n] + diff[NN + n] + diff[2 * NN + n]) * (1.0f / 3.0f);
        acc += (1.0f - dm) * (g_inst[0][n] - 0.5f * delta)
             + dm * (g_inst[1][n] + 0.5f * delta);
    }
    sred[tid] = acc;
    __syncthreads();
    for (int o = 512; o; o >>= 1) {
        if (tid < o) sred[tid] += sred[tid + o];
        __syncthreads();
    }
    if (tid == 0) out[0] = sred[0];
}

// ---------------------------------------------------------------------------
extern "C" void kernel_launch(void* const* d_in, const int* in_sizes, int n_in,
                              void* d_out, int out_size) {
    const float* pA   = (const float*)d_in[0];  // predictions_fir [S,B,N,D]
    const float* pB   = (const float*)d_in[1];  // predictions_sec [S,B,N,D]
    const float* gt   = (const float*)d_in[2];  // gt_lane [B,L,D]
    const float* diff = (const float*)d_in[3];  // diff [S,N]
    float* out = (float*)d_out;

    int blocks_cost = (2 * SS * BB * NN) / 8;   // 48000
    k_cost<<<blocks_cost, 256>>>(pA, pB, gt);

    k_assign<<<2 * SS * BB, 256>>>();           // 192 blocks

    dim3 gcls(8, 2);
    k_cls<<<gcls, 256>>>();

    k_matched<<<2 * SS * BB * LL, 32>>>(pA, pB, gt);

    k_final<<<1, 1024>>>(diff, out);
}

// round 3
// speedup vs baseline: 2.6969x; 1.1671x over previous
#include <cuda_runtime.h>
#include <math.h>

// Problem constants
#define SS 3       // REFINE_LAYERS
#define BB 32      // batch
#define NN 2000    // priors
#define LL 4       // max lanes
#define DD 78      // 2 + 4 + 72
#define NP 72      // num points offsets

// Scratch (device globals; no allocation allowed)
__device__ float  g_cost[2][SS][BB][LL][NN];   // transposed: coalesced argmin reads
__device__ float2 g_clslog[2][SS][BB][NN];
__device__ int    g_rows[2][SS][BB][LL];
__device__ float  g_inst[2][NN];
__device__ float  g_regpart[2][SS][BB][LL];
__device__ float  g_ioupart[2][SS][BB][LL];

// ---------------------------------------------------------------------------
// Kernel 1: cost matrix + per-prior log-softmax.
// One warp per (branch, s, b, n). 8 warps/block; NN % 8 == 0 so every block
// has a single (branch,s,b). Fast-math softmax (score feeds a discrete argmin
// with O(0.01) gaps; ~1e-6 error cannot flip it).
// ---------------------------------------------------------------------------
__global__ void __launch_bounds__(256) k_cost(const float* __restrict__ pA,
                                              const float* __restrict__ pB,
                                              const float* __restrict__ gt) {
    __shared__ float sq[LL][NP];    // gt offsets * (1/799)
    __shared__ float sraw[LL][4];   // raw gt dims 2..5 (geo)
    const int wib  = threadIdx.x >> 5;
    const int lane = threadIdx.x & 31;
    int gw = blockIdx.x * 8 + wib;

    int n = gw % NN; int t = gw / NN;
    int b = t % BB;  t /= BB;
    int s = t % SS;  int br = t / SS;

    for (int i = threadIdx.x; i < LL * DD; i += 256) {
        int l = i / DD, d = i % DD;
        float v = gt[b * LL * DD + i];
        if (d >= 6)      sq[l][d - 6]   = v * (1.0f / 799.0f);
        else if (d >= 2) sraw[l][d - 2] = v;
    }
    __syncthreads();

    const float* p = (br ? pB : pA) + ((size_t)((s * BB + b) * NN + n)) * DD;
    float v0 = p[lane];
    float v1 = p[lane + 32];
    float v2 = (lane < 14) ? p[lane + 64] : 0.0f;

    float p0 = __shfl_sync(0xffffffffu, v0, 0);
    float p1 = __shfl_sync(0xffffffffu, v0, 1);
    // fast log-softmax
    float mx  = fmaxf(p0, p1);
    float e0  = __expf(p0 - mx), e1 = __expf(p1 - mx);
    float sum = e0 + e1;
    float lse = mx + __logf(sum);
    float lp0 = p0 - lse, lp1 = p1 - lse;
    float score = __fdividef(e1, sum);

    float c[LL];
    #pragma unroll
    for (int l = 0; l < LL; l++) {
        float off = 0.0f, geo = 0.0f;
        if (lane >= 6)      off  = fabsf(v0 - sq[l][lane - 6]);
        else if (lane >= 2) geo  = fabsf(v0 - sraw[l][lane - 2]);
        off += fabsf(v1 - sq[l][lane + 26]);
        if (lane < 14) off += fabsf(v2 - sq[l][lane + 58]);
        c[l] = geo + off * (1.0f / 72.0f);
    }
    #pragma unroll
    for (int o = 16; o; o >>= 1) {
        #pragma unroll
        for (int l = 0; l < LL; l++)
            c[l] += __shfl_xor_sync(0xffffffffu, c[l], o);
    }
    // lanes 0-3 store the 4 cost columns; lane 4 stores clslog
    float cs = (lane & 2) ? ((lane & 1) ? c[3] : c[2])
                          : ((lane & 1) ? c[1] : c[0]);
    if (lane < 4)
        g_cost[br][s][b][lane][n] = cs - score;
    if (lane == 4)
        g_clslog[br][s][b][n] = make_float2(lp0, lp1);
}

// ---------------------------------------------------------------------------
// Kernel 2: greedy assignment without replacement, per (branch,s,b).
// L=4 sequential argmins over N; tie-break = lowest index (jnp.argmin).
// ---------------------------------------------------------------------------
__global__ void __launch_bounds__(256) k_assign() {
    int b = blockIdx.x % BB; int t = blockIdx.x / BB;
    int s = t % SS; int br = t / SS;
    const int wib = threadIdx.x >> 5, lane = threadIdx.x & 31;

    __shared__ float swv[8];
    __shared__ int   swi[8];
    __shared__ int   chosen[LL];

    for (int l = 0; l < LL; l++) {
        const float* cost = &g_cost[br][s][b][l][0];
        float best = INFINITY; int bi = NN;
        for (int n = threadIdx.x; n < NN; n += 256) {
            bool used = false;
            #pragma unroll
            for (int j = 0; j < 3; j++) used |= (j < l) && (chosen[j] == n);
            float v = used ? INFINITY : __ldg(&cost[n]);
            if (v < best) { best = v; bi = n; }   // ascending n -> first idx on tie
        }
        #pragma unroll
        for (int o = 16; o; o >>= 1) {
            float ov = __shfl_xor_sync(0xffffffffu, best, o);
            int   oi = __shfl_xor_sync(0xffffffffu, bi,   o);
            if (ov < best || (ov == best && oi < bi)) { best = ov; bi = oi; }
        }
        if (lane == 0) { swv[wib] = best; swi[wib] = bi; }
        __syncthreads();
        if (threadIdx.x == 0) {
            float bv = swv[0]; int bix = swi[0];
            #pragma unroll
            for (int w = 1; w < 8; w++) {
                if (swv[w] < bv || (swv[w] == bv && swi[w] < bix)) {
                    bv = swv[w]; bix = swi[w];
                }
            }
            chosen[l] = bix; g_rows[br][s][b][l] = bix;
        }
        __syncthreads();
    }
}

// ---------------------------------------------------------------------------
// Kernel 3 (fused): blocks 0-15 = focal cls loss; blocks 16-111 = matched
// smooth-L1 + line-IoU partials (8 warps/block, one item each).
// ---------------------------------------------------------------------------
__global__ void __launch_bounds__(256) k_clsmatched(const float* __restrict__ pA,
                                                    const float* __restrict__ pB,
                                                    const float* __restrict__ gt) {
    if (blockIdx.x < 16) {
        // ---- cls part ----
        __shared__ int srows[SS * BB * LL];   // 384
        int br = blockIdx.x >> 3;
        int n  = (blockIdx.x & 7) * 256 + threadIdx.x;

        const int* rsrc = &g_rows[br][0][0][0];
        for (int i = threadIdx.x; i < SS * BB * LL; i += 256) srows[i] = rsrc[i];
        __syncthreads();
        if (n >= NN) return;

        const float2* lpbase = &g_clslog[br][0][0][0];
        float acc = 0.0f;
        #pragma unroll 4
        for (int sb = 0; sb < SS * BB; sb++) {
            float2 lp = lpbase[sb * NN + n];
            const int* r = &srows[sb * 4];
            bool matched = (r[0] == n) | (r[1] == n) | (r[2] == n) | (r[3] == n);
            float logpt = matched ? lp.y : lp.x;
            float pt = __expf(logpt);
            float a = matched ? 0.9f : 0.1f;
            float om = 1.0f - pt;
            acc += -a * om * om * logpt;
        }
        g_inst[br][n] = acc * (1.0f / 96.0f) * 2.0f;  // /(B*S), * CLS_W
    } else {
        // ---- matched part: one warp per (br,s,b,l) ----
        int wib = threadIdx.x >> 5, lane = threadIdx.x & 31;
        int id = (blockIdx.x - 16) * 8 + wib;   // [0, 768)
        int l = id % LL; int t = id / LL;
        int b = t % BB;  t /= BB;
        int s = t % SS;  int br = t / SS;

        int r = g_rows[br][s][b][l];
        const float* pm = (br ? pB : pA) + ((size_t)((s * BB + b) * NN + r)) * DD;
        const float* tg = gt + (b * LL + l) * DD;

        float sl = 0.0f;
        if (lane < 4) {
            const float scv[4] = {71.0f, 799.0f, 180.0f, 71.0f};
            float d = pm[2 + lane] * scv[lane] - tg[2 + lane] * scv[lane];
            float ad = fabsf(d);
            sl = (ad < 1.0f) ? 0.5f * d * d : ad - 0.5f;
        }
        float ovr = 0.0f, uni = 0.0f;
        #pragma unroll
        for (int jj = 0; jj < 3; jj++) {
            int j = lane + jj * 32;
            if (j < NP) {
                float rp = pm[6 + j] * 799.0f;
                float rt = tg[6 + j];
                bool inv = (rt < 0.0f) || (rt >= 800.0f);
                float o = fminf(rp + 15.0f, rt + 15.0f) - fmaxf(rp - 15.0f, rt - 15.0f);
                float u = fmaxf(rp + 15.0f, rt + 15.0f) - fminf(rp - 15.0f, rt - 15.0f);
                if (!inv) { ovr += o; uni += u; }
            }
        }
        #pragma unroll
        for (int o = 16; o; o >>= 1) {
            sl  += __shfl_xor_sync(0xffffffffu, sl,  o);
            ovr += __shfl_xor_sync(0xffffffffu, ovr, o);
            uni += __shfl_xor_sync(0xffffffffu, uni, o);
        }
        if (lane == 0) {
            float iou = ovr / (uni + 1e-9f);
            g_regpart[br][s][b][l] = (sl * 0.25f) / (float)LL;
            g_ioupart[br][s][b][l] = (1.0f - iou) / (float)LL;
        }
    }
}

// ---------------------------------------------------------------------------
// Kernel 4: finalize. reg/iou reduce + scatter into inst, median via bitonic
// sort (2048 padded), weighted sum.
// ---------------------------------------------------------------------------
__global__ void __launch_bounds__(1024) k_final(const float* __restrict__ diff,
                                                float* __restrict__ out) {
    __shared__ float sx[2048];
    __shared__ float sred[1024];
    int tid = threadIdx.x;

    if (tid < 2 * LL) {
        int br = tid >> 2, l = tid & 3;
        const float* rp = &g_regpart[br][0][0][0];
        const float* ip = &g_ioupart[br][0][0][0];
        float rs = 0.0f, is = 0.0f;
        for (int sb = 0; sb < SS * BB; sb++) {
            rs += rp[sb * LL + l];
            is += ip[sb * LL + l];
        }
        rs *= (1.0f / 96.0f);
        is *= (1.0f / 96.0f);
        int row = g_rows[br][SS - 1][BB - 1][l];
        g_inst[br][row] += rs * 0.5f + is * 2.0f;  // REG_W, IOU_W
    }
    __syncthreads();

    for (int n = tid; n < 2048; n += 1024)
        sx[n] = (n < NN) ? (g_inst[0][n] - g_inst[1][n]) : INFINITY;

    for (int k = 2; k <= 2048; k <<= 1) {
        for (int j = k >> 1; j > 0; j >>= 1) {
            __syncthreads();
            for (int i = tid; i < 2048; i += 1024) {
                int ixj = i ^ j;
                if (ixj > i) {
                    float a = sx[i], bb2 = sx[ixj];
                    bool up = ((i & k) == 0);
                    if ((a > bb2) == up) { sx[i] = bb2; sx[ixj] = a; }
                }
            }
        }
    }
    __syncthreads();
    float delta = 0.5f * (sx[999] + sx[1000]);

    float acc = 0.0f;
    for (int n = tid; n < NN; n += 1024) {
        float dm = (diff[n] + diff[NN + n] + diff[2 * NN + n]) * (1.0f / 3.0f);
        acc += (1.0f - dm) * (g_inst[0][n] - 0.5f * delta)
             + dm * (g_inst[1][n] + 0.5f * delta);
    }
    sred[tid] = acc;
    __syncthreads();
    for (int o = 512; o; o >>= 1) {
        if (tid < o) sred[tid] += sred[tid + o];
        __syncthreads();
    }
    if (tid == 0) out[0] = sred[0];
}

// ---------------------------------------------------------------------------
extern "C" void kernel_launch(void* const* d_in, const int* in_sizes, int n_in,
                              void* d_out, int out_size) {
    const float* pA   = (const float*)d_in[0];  // predictions_fir [S,B,N,D]
    const float* pB   = (const float*)d_in[1];  // predictions_sec [S,B,N,D]
    const float* gt   = (const float*)d_in[2];  // gt_lane [B,L,D]
    const float* diff = (const float*)d_in[3];  // diff [S,N]
    float* out = (float*)d_out;

    int blocks_cost = (2 * SS * BB * NN) / 8;   // 48000
    k_cost<<<blocks_cost, 256>>>(pA, pB, gt);

    k_assign<<<2 * SS * BB, 256>>>();           // 192 blocks

    k_clsmatched<<<16 + 96, 256>>>(pA, pB, gt); // fused cls + matched

    k_final<<<1, 1024>>>(diff, out);
}

// round 4
// speedup vs baseline: 4.5505x; 1.6873x over previous
#include <cuda_runtime.h>
#include <math.h>

// Problem constants
#define SS 3       // REFINE_LAYERS
#define BB 32      // batch
#define NN 2000    // priors
#define LL 4       // max lanes
#define DD 78      // 2 + 4 + 72
#define NP 72      // num points offsets
#define PRI 80     // priors per k_cost block

// Scratch (device globals; no allocation allowed)
__device__ float  g_cost[2][SS][BB][LL][NN];   // transposed: coalesced argmin reads
__device__ float2 g_clslog[2][SS][BB][NN];
__device__ int    g_rows[2][SS][BB][LL];
__device__ float  g_inst[2][NN];
__device__ float  g_regpart[2][SS][BB][LL];
__device__ float  g_ioupart[2][SS][BB][LL];

// ---------------------------------------------------------------------------
// Kernel 1: cost matrix + per-prior log-softmax.
// Thread-per-(prior, gt-lane): block stages 80 prior rows + gt in shared,
// each thread serially accumulates |p - t| with float4 shared loads. No
// shuffle reductions. Row stride 84 -> conflict-free LDS.128 + alignment.
// ---------------------------------------------------------------------------
__global__ void __launch_bounds__(320) k_cost(const float* __restrict__ pA,
                                              const float* __restrict__ pB,
                                              const float* __restrict__ gt) {
    __shared__ float sp[PRI][84];   // prediction rows, dims at [2..79]
    __shared__ float sq[LL][NP];    // gt offsets * (1/799)
    __shared__ float sraw[LL][4];   // raw gt dims 2..5
    const int tid = threadIdx.x;

    int chunk = blockIdx.x % (NN / PRI);   // 25 chunks
    int t = blockIdx.x / (NN / PRI);
    int b = t % BB;  t /= BB;
    int s = t % SS;  int br = t / SS;
    int n0 = chunk * PRI;

    // gt staging (312 values)
    for (int i = tid; i < LL * DD; i += 320) {
        int l = i / DD, d = i % DD;
        float v = gt[b * LL * DD + i];
        if (d >= 6)      sq[l][d - 6]   = v * (1.0f / 799.0f);
        else if (d >= 2) sraw[l][d - 2] = v;
    }
    // prediction staging: 80 rows x 78 floats, float2 granularity
    const float2* p2 = (const float2*)((br ? pB : pA)
                     + ((size_t)((s * BB + b) * NN + n0)) * DD);
    for (int i = tid; i < PRI * DD / 2; i += 320) {  // 3120
        float2 v = p2[i];
        int e = 2 * i;
        int r = e / DD, c = e % DD;
        *(float2*)&sp[r][2 + c] = v;    // (84r + 2 + c) even -> 8B aligned
    }
    __syncthreads();

    int pr = tid >> 2, l = tid & 3;
    float p0 = sp[pr][2], p1 = sp[pr][3];
    float mx  = fmaxf(p0, p1);
    float e0  = __expf(p0 - mx), e1 = __expf(p1 - mx);
    float sum = e0 + e1;
    float lse = mx + __logf(sum);
    float score = __fdividef(e1, sum);

    float4 g4 = *(const float4*)&sp[pr][4];    // dims 2..5
    float4 t4 = *(const float4*)&sraw[l][0];
    float geo = fabsf(g4.x - t4.x) + fabsf(g4.y - t4.y)
              + fabsf(g4.z - t4.z) + fabsf(g4.w - t4.w);

    float off = 0.0f;
    #pragma unroll
    for (int k = 0; k < NP / 4; k++) {
        float4 a = *(const float4*)&sp[pr][8 + 4 * k];
        float4 q = *(const float4*)&sq[l][4 * k];
        off += fabsf(a.x - q.x) + fabsf(a.y - q.y)
             + fabsf(a.z - q.z) + fabsf(a.w - q.w);
    }
    g_cost[br][s][b][l][n0 + pr] = geo + off * (1.0f / 72.0f) - score;
    if (l == 0)
        g_clslog[br][s][b][n0 + pr] = make_float2(p0 - lse, p1 - lse);
}

// ---------------------------------------------------------------------------
// Kernel 2: greedy assignment without replacement, per (branch,s,b).
// L=4 sequential argmins over N; tie-break = lowest index (jnp.argmin).
// ---------------------------------------------------------------------------
__global__ void __launch_bounds__(256) k_assign() {
    int b = blockIdx.x % BB; int t = blockIdx.x / BB;
    int s = t % SS; int br = t / SS;
    const int wib = threadIdx.x >> 5, lane = threadIdx.x & 31;

    __shared__ float swv[8];
    __shared__ int   swi[8];
    __shared__ int   chosen[LL];

    for (int l = 0; l < LL; l++) {
        const float* cost = &g_cost[br][s][b][l][0];
        float best = INFINITY; int bi = NN;
        for (int n = threadIdx.x; n < NN; n += 256) {
            bool used = false;
            #pragma unroll
            for (int j = 0; j < 3; j++) used |= (j < l) && (chosen[j] == n);
            float v = used ? INFINITY : __ldg(&cost[n]);
            if (v < best) { best = v; bi = n; }   // ascending n -> first idx on tie
        }
        #pragma unroll
        for (int o = 16; o; o >>= 1) {
            float ov = __shfl_xor_sync(0xffffffffu, best, o);
            int   oi = __shfl_xor_sync(0xffffffffu, bi,   o);
            if (ov < best || (ov == best && oi < bi)) { best = ov; bi = oi; }
        }
        if (lane == 0) { swv[wib] = best; swi[wib] = bi; }
        __syncthreads();
        if (threadIdx.x == 0) {
            float bv = swv[0]; int bix = swi[0];
            #pragma unroll
            for (int w = 1; w < 8; w++) {
                if (swv[w] < bv || (swv[w] == bv && swi[w] < bix)) {
                    bv = swv[w]; bix = swi[w];
                }
            }
            chosen[l] = bix; g_rows[br][s][b][l] = bix;
        }
        __syncthreads();
    }
}

// ---------------------------------------------------------------------------
// Kernel 3 (fused): blocks 0-15 = focal cls loss; blocks 16-111 = matched
// smooth-L1 + line-IoU partials (8 warps/block, one item each).
// ---------------------------------------------------------------------------
__global__ void __launch_bounds__(256) k_clsmatched(const float* __restrict__ pA,
                                                    const float* __restrict__ pB,
                                                    const float* __restrict__ gt) {
    if (blockIdx.x < 16) {
        __shared__ int srows[SS * BB * LL];   // 384
        int br = blockIdx.x >> 3;
        int n  = (blockIdx.x & 7) * 256 + threadIdx.x;

        const int* rsrc = &g_rows[br][0][0][0];
        for (int i = threadIdx.x; i < SS * BB * LL; i += 256) srows[i] = rsrc[i];
        __syncthreads();
        if (n >= NN) return;

        const float2* lpbase = &g_clslog[br][0][0][0];
        float acc = 0.0f;
        #pragma unroll 4
        for (int sb = 0; sb < SS * BB; sb++) {
            float2 lp = lpbase[sb * NN + n];
            const int* r = &srows[sb * 4];
            bool matched = (r[0] == n) | (r[1] == n) | (r[2] == n) | (r[3] == n);
            float logpt = matched ? lp.y : lp.x;
            float pt = __expf(logpt);
            float a = matched ? 0.9f : 0.1f;
            float om = 1.0f - pt;
            acc += -a * om * om * logpt;
        }
        g_inst[br][n] = acc * (1.0f / 96.0f) * 2.0f;  // /(B*S), * CLS_W
    } else {
        int wib = threadIdx.x >> 5, lane = threadIdx.x & 31;
        int id = (blockIdx.x - 16) * 8 + wib;   // [0, 768)
        int l = id % LL; int t = id / LL;
        int b = t % BB;  t /= BB;
        int s = t % SS;  int br = t / SS;

        int r = g_rows[br][s][b][l];
        const float* pm = (br ? pB : pA) + ((size_t)((s * BB + b) * NN + r)) * DD;
        const float* tg = gt + (b * LL + l) * DD;

        float sl = 0.0f;
        if (lane < 4) {
            const float scv[4] = {71.0f, 799.0f, 180.0f, 71.0f};
            float d = pm[2 + lane] * scv[lane] - tg[2 + lane] * scv[lane];
            float ad = fabsf(d);
            sl = (ad < 1.0f) ? 0.5f * d * d : ad - 0.5f;
        }
        float ovr = 0.0f, uni = 0.0f;
        #pragma unroll
        for (int jj = 0; jj < 3; jj++) {
            int j = lane + jj * 32;
            if (j < NP) {
                float rp = pm[6 + j] * 799.0f;
                float rt = tg[6 + j];
                bool inv = (rt < 0.0f) || (rt >= 800.0f);
                float o = fminf(rp + 15.0f, rt + 15.0f) - fmaxf(rp - 15.0f, rt - 15.0f);
                float u = fmaxf(rp + 15.0f, rt + 15.0f) - fminf(rp - 15.0f, rt - 15.0f);
                if (!inv) { ovr += o; uni += u; }
            }
        }
        #pragma unroll
        for (int o = 16; o; o >>= 1) {
            sl  += __shfl_xor_sync(0xffffffffu, sl,  o);
            ovr += __shfl_xor_sync(0xffffffffu, ovr, o);
            uni += __shfl_xor_sync(0xffffffffu, uni, o);
        }
        if (lane == 0) {
            float iou = ovr / (uni + 1e-9f);
            g_regpart[br][s][b][l] = (sl * 0.25f) / (float)LL;
            g_ioupart[br][s][b][l] = (1.0f - iou) / (float)LL;
        }
    }
}

// ---------------------------------------------------------------------------
// Kernel 4: finalize. reg/iou reduce + scatter, exact radix-select median
// (order stats 999 & 1000 over order-preserving uint keys), weighted sum.
// ---------------------------------------------------------------------------
__global__ void __launch_bounds__(1024) k_final(const float* __restrict__ diff,
                                                float* __restrict__ out) {
    __shared__ unsigned su[NN];
    __shared__ int hist[256];
    __shared__ int s_sel, s_k;
    __shared__ float s_med[2];
    __shared__ float sred[1024];
    int tid = threadIdx.x;

    // step 1: per-(branch,l) deterministic reduce + inst scatter
    if (tid < 2 * LL) {
        int br = tid >> 2, l = tid & 3;
        const float* rp = &g_regpart[br][0][0][0];
        const float* ip = &g_ioupart[br][0][0][0];
        float rs = 0.0f, is = 0.0f;
        for (int sb = 0; sb < SS * BB; sb++) {
            rs += rp[sb * LL + l];
            is += ip[sb * LL + l];
        }
        rs *= (1.0f / 96.0f);
        is *= (1.0f / 96.0f);
        int row = g_rows[br][SS - 1][BB - 1][l];
        g_inst[br][row] += rs * 0.5f + is * 2.0f;  // REG_W, IOU_W
    }
    __syncthreads();

    // step 2: order-preserving uint keys of x = instA - instB
    for (int n = tid; n < NN; n += 1024) {
        float x = g_inst[0][n] - g_inst[1][n];
        unsigned u = __float_as_uint(x);
        su[n] = (u & 0x80000000u) ? ~u : (u | 0x80000000u);
    }
    __syncthreads();

    // step 3: exact radix select for ranks 999 and 1000
    for (int rsel = 0; rsel < 2; rsel++) {
        int k = 999 + rsel;
        unsigned prefix = 0;
        for (int shift = 24; shift >= 0; shift -= 8) {
            if (tid < 256) hist[tid] = 0;
            __syncthreads();
            unsigned mask = (shift == 24) ? 0u : (0xFFFFFFFFu << (shift + 8));
            for (int i = tid; i < NN; i += 1024) {
                unsigned u = su[i];
                if ((u & mask) == prefix)
                    atomicAdd(&hist[(u >> shift) & 255], 1);
            }
            __syncthreads();
            if (tid < 32) {
                int base = tid * 8, ssum = 0;
                int c[8];
                #pragma unroll
                for (int j = 0; j < 8; j++) { c[j] = hist[base + j]; ssum += c[j]; }
                int run = ssum;
                #pragma unroll
                for (int o = 1; o < 32; o <<= 1) {
                    int v = __shfl_up_sync(0xffffffffu, run, o);
                    if (tid >= o) run += v;
                }
                int excl = run - ssum;
                if (k >= excl && k < run) {
                    int acc = excl;
                    #pragma unroll
                    for (int j = 0; j < 8; j++) {
                        if (k < acc + c[j]) { s_sel = base + j; s_k = k - acc; break; }
                        acc += c[j];
                    }
                }
            }
            __syncthreads();
            prefix |= ((unsigned)s_sel) << shift;
            k = s_k;
            __syncthreads();
        }
        if (tid == 0) {
            unsigned u = prefix;
            float v = (u & 0x80000000u) ? __uint_as_float(u ^ 0x80000000u)
                                        : __uint_as_float(~u);
            s_med[rsel] = v;
        }
        __syncthreads();
    }
    float delta = 0.5f * (s_med[0] + s_med[1]);

    // step 4: total = sum (1-dm)*(A - d/2) + dm*(B + d/2)
    float acc = 0.0f;
    for (int n = tid; n < NN; n += 1024) {
        float dm = (diff[n] + diff[NN + n] + diff[2 * NN + n]) * (1.0f / 3.0f);
        acc += (1.0f - dm) * (g_inst[0][n] - 0.5f * delta)
             + dm * (g_inst[1][n] + 0.5f * delta);
    }
    sred[tid] = acc;
    __syncthreads();
    for (int o = 512; o; o >>= 1) {
        if (tid < o) sred[tid] += sred[tid + o];
        __syncthreads();
    }
    if (tid == 0) out[0] = sred[0];
}

// ---------------------------------------------------------------------------
extern "C" void kernel_launch(void* const* d_in, const int* in_sizes, int n_in,
                              void* d_out, int out_size) {
    const float* pA   = (const float*)d_in[0];  // predictions_fir [S,B,N,D]
    const float* pB   = (const float*)d_in[1];  // predictions_sec [S,B,N,D]
    const float* gt   = (const float*)d_in[2];  // gt_lane [B,L,D]
    const float* diff = (const float*)d_in[3];  // diff [S,N]
    float* out = (float*)d_out;

    int blocks_cost = 2 * SS * BB * (NN / PRI);   // 4800
    k_cost<<<blocks_cost, 320>>>(pA, pB, gt);

    k_assign<<<2 * SS * BB, 256>>>();             // 192 blocks

    k_clsmatched<<<16 + 96, 256>>>(pA, pB, gt);   // fused cls + matched

    k_final<<<1, 1024>>>(diff, out);
}